// round 2
// baseline (speedup 1.0000x reference)
#include <cuda_runtime.h>
#include <math.h>
#include <stdint.h>

// Problem constants
#define L_   4
#define DM_  768
#define DI_  1536
#define DS_  16
#define DR_  48
#define KC_  4
#define V_   32000
#define B_   2
#define S_   2048
#define BS_  (B_*S_)       // 4096 tokens
#define XZ_  (2*DI_)       // 3072
#define DBC_ (DR_+2*DS_)   // 80

// ---------------- scratch (static device memory; no allocations) ----------------
__device__ float g_h   [BS_*DM_];
__device__ float g_xn  [BS_*DM_];
__device__ float g_xz  [BS_*XZ_];
__device__ float g_xc  [BS_*DI_];
__device__ float g_dbc [BS_*DBC_];
__device__ float g_dt  [BS_*DI_];
__device__ float g_y   [BS_*DI_];
__device__ float g_comb[BS_*2*DM_];
__device__ float g_rownll[BS_];

// ---------------- embedding gather (optionally sequence-reversed) ----------------
__global__ void embed_k(const int* __restrict__ ids, const float* __restrict__ emb,
                        float* __restrict__ h, int flip) {
    int r = blockIdx.x;              // token index in [0, BS)
    int b = r / S_, s = r % S_;
    int s2 = flip ? (S_ - 1 - s) : s;
    int tok = ids[b * S_ + s2];
    const float* e = emb + (size_t)tok * DM_;
    float* o = h + (size_t)r * DM_;
    for (int i = threadIdx.x; i < DM_; i += blockDim.x) o[i] = e[i];
}

// ---------------- RMSNorm (optionally writing flipped / offset / strided) ----------------
__global__ void rms_k(const float* __restrict__ x, const float* __restrict__ w,
                      float* __restrict__ out, int ldo, int off, int flip) {
    int r = blockIdx.x;
    const float* xr = x + (size_t)r * DM_;
    float ss = 0.f;
    for (int i = threadIdx.x; i < DM_; i += blockDim.x) { float v = xr[i]; ss += v * v; }
    __shared__ float red[32];
    #pragma unroll
    for (int o = 16; o; o >>= 1) ss += __shfl_xor_sync(~0u, ss, o);
    if ((threadIdx.x & 31) == 0) red[threadIdx.x >> 5] = ss;
    __syncthreads();
    if (threadIdx.x < 32) {
        float v = (threadIdx.x < (blockDim.x >> 5)) ? red[threadIdx.x] : 0.f;
        #pragma unroll
        for (int o = 16; o; o >>= 1) v += __shfl_xor_sync(~0u, v, o);
        if (threadIdx.x == 0) red[0] = v;
    }
    __syncthreads();
    float scale = rsqrtf(red[0] / (float)DM_ + 1e-5f);
    int ro = r;
    if (flip) { int b = r / S_, s = r % S_; ro = b * S_ + (S_ - 1 - s); }
    float* o = out + (size_t)ro * ldo + off;
    for (int i = threadIdx.x; i < DM_; i += blockDim.x) o[i] = xr[i] * scale * w[i];
}

// ---------------- depthwise causal conv (kernel 4) + SiLU ----------------
__global__ void conv_k(const float* __restrict__ xz, const float* __restrict__ cw,
                       const float* __restrict__ cb, float* __restrict__ xc) {
    int idx = blockIdx.x * blockDim.x + threadIdx.x;
    if (idx >= BS_ * DI_) return;
    int d = idx % DI_;
    int r = idx / DI_;
    int s = r % S_;
    float acc = cb[d];
    #pragma unroll
    for (int k = 0; k < KC_; k++) {
        int sp = s - (KC_ - 1) + k;
        if (sp >= 0) acc += xz[(size_t)(r - s + sp) * XZ_ + d] * cw[d * KC_ + k];
    }
    float sig = 1.f / (1.f + expf(-acc));
    xc[idx] = acc * sig;
}

// ---------------- generic GEMM: C[M,N] = A[M,K] * B[N,K]^T  (row-major, K contiguous) ----------------
// bias (per-col) + softplus activation (act==1) + accumulate-into-C (accum==1) fusions.
// Requirements used here: M % 64 == 0, K % 16 == 0 (true for every call site). N guarded.
__global__ __launch_bounds__(256) void gemm_k(
    const float* __restrict__ A, int lda,
    const float* __restrict__ Bm, int ldb,
    float* __restrict__ C, int ldc,
    int M, int N, int K,
    const float* __restrict__ bias, int act, int accum)
{
    __shared__ float As[16][68];
    __shared__ float Bs[16][68];
    int bm = blockIdx.y * 64, bn = blockIdx.x * 64;
    int tid = threadIdx.x;
    int lr = tid >> 2;            // 0..63  row within tile to load
    int lk = (tid & 3) * 4;       // 0,4,8,12  float4 position along K
    int tm = tid >> 4;            // 0..15 output row group
    int tn = tid & 15;            // 0..15 output col group

    float acc[4][4];
    #pragma unroll
    for (int i = 0; i < 4; i++)
        #pragma unroll
        for (int j = 0; j < 4; j++) acc[i][j] = 0.f;

    const float* Ap = A + (size_t)(bm + lr) * lda + lk;
    bool bok = (bn + lr) < N;
    const float* Bp = Bm + (size_t)(bok ? (bn + lr) : 0) * ldb + lk;

    for (int k0 = 0; k0 < K; k0 += 16) {
        float4 av = *(const float4*)(Ap + k0);
        float4 bv = bok ? *(const float4*)(Bp + k0) : make_float4(0.f, 0.f, 0.f, 0.f);
        As[lk + 0][lr] = av.x; As[lk + 1][lr] = av.y; As[lk + 2][lr] = av.z; As[lk + 3][lr] = av.w;
        Bs[lk + 0][lr] = bv.x; Bs[lk + 1][lr] = bv.y; Bs[lk + 2][lr] = bv.z; Bs[lk + 3][lr] = bv.w;
        __syncthreads();
        #pragma unroll
        for (int k = 0; k < 16; k++) {
            float4 a = *(const float4*)&As[k][tm * 4];
            float4 b = *(const float4*)&Bs[k][tn * 4];
            acc[0][0] += a.x * b.x; acc[0][1] += a.x * b.y; acc[0][2] += a.x * b.z; acc[0][3] += a.x * b.w;
            acc[1][0] += a.y * b.x; acc[1][1] += a.y * b.y; acc[1][2] += a.y * b.z; acc[1][3] += a.y * b.w;
            acc[2][0] += a.z * b.x; acc[2][1] += a.z * b.y; acc[2][2] += a.z * b.z; acc[2][3] += a.z * b.w;
            acc[3][0] += a.w * b.x; acc[3][1] += a.w * b.y; acc[3][2] += a.w * b.z; acc[3][3] += a.w * b.w;
        }
        __syncthreads();
    }

    #pragma unroll
    for (int i = 0; i < 4; i++) {
        int row = bm + tm * 4 + i;
        #pragma unroll
        for (int j = 0; j < 4; j++) {
            int col = bn + tn * 4 + j;
            if (col < N) {
                float v = acc[i][j];
                if (bias) v += bias[col];
                if (act == 1) v = (v > 20.f) ? v : log1pf(expf(v));  // softplus
                float* cp = C + (size_t)row * ldc + col;
                if (accum) v += *cp;
                *cp = v;
            }
        }
    }
}

// ---------------- selective scan: one thread per (batch, channel); 16 states in registers ----------------
// Fuses: y = scan_out + Dp*xc, then y *= silu(z)
__global__ void scan_k(const float* __restrict__ dt, const float* __restrict__ dbc,
                       const float* __restrict__ xc, const float* __restrict__ xz,
                       const float* __restrict__ Alog, const float* __restrict__ Dp,
                       float* __restrict__ y) {
    int t = blockIdx.x * blockDim.x + threadIdx.x;
    if (t >= B_ * DI_) return;
    int b = t / DI_, d = t % DI_;
    float a[DS_], h[DS_];
    #pragma unroll
    for (int n = 0; n < DS_; n++) { a[n] = -expf(Alog[d * DS_ + n]); h[n] = 0.f; }
    float Dpd = Dp[d];
    for (int s = 0; s < S_; s++) {
        size_t r = (size_t)b * S_ + s;
        float dtv = dt[r * DI_ + d];
        float xv  = xc[r * DI_ + d];
        float zv  = xz[r * XZ_ + DI_ + d];
        const float* bc = dbc + r * DBC_;
        float dx = dtv * xv;
        float yv = 0.f;
        #pragma unroll
        for (int n = 0; n < DS_; n++) {
            float e = expf(dtv * a[n]);
            h[n] = e * h[n] + dx * bc[DR_ + n];         // B_t broadcast within warp
            yv  += h[n] * bc[DR_ + DS_ + n];            // C_t broadcast within warp
        }
        yv += Dpd * xv;
        float sil = zv / (1.f + expf(-zv));
        y[r * DI_ + d] = yv * sil;
    }
}

// ---------------- per-row logsumexp + NLL ----------------
__global__ void loss_row_k(const float* __restrict__ logits, const int* __restrict__ labels,
                           float* __restrict__ rownll) {
    int r = blockIdx.x;
    const float* lr = logits + (size_t)r * V_;
    __shared__ float red[32];
    float m = -INFINITY;
    for (int i = threadIdx.x; i < V_; i += blockDim.x) m = fmaxf(m, lr[i]);
    #pragma unroll
    for (int o = 16; o; o >>= 1) m = fmaxf(m, __shfl_xor_sync(~0u, m, o));
    if ((threadIdx.x & 31) == 0) red[threadIdx.x >> 5] = m;
    __syncthreads();
    if (threadIdx.x == 0) { float v = red[0]; for (int i = 1; i < 8; i++) v = fmaxf(v, red[i]); red[0] = v; }
    __syncthreads();
    m = red[0];
    __syncthreads();
    float sum = 0.f;
    for (int i = threadIdx.x; i < V_; i += blockDim.x) sum += expf(lr[i] - m);
    #pragma unroll
    for (int o = 16; o; o >>= 1) sum += __shfl_xor_sync(~0u, sum, o);
    if ((threadIdx.x & 31) == 0) red[threadIdx.x >> 5] = sum;
    __syncthreads();
    if (threadIdx.x == 0) {
        float v = 0.f;
        for (int i = 0; i < 8; i++) v += red[i];
        int lab = labels[r];
        float nll = 0.f;
        if (lab != -100) nll = (m + logf(v)) - lr[lab];
        rownll[r] = nll;
    }
}

// ---------------- deterministic final reduction ----------------
__global__ void loss_red_k(const float* __restrict__ rownll, const int* __restrict__ labels,
                           float* __restrict__ out) {
    __shared__ float rs[32]; __shared__ int rc[32];
    float s = 0.f; int c = 0;
    for (int i = threadIdx.x; i < BS_; i += blockDim.x) {
        s += rownll[i];
        if (labels[i] != -100) c++;
    }
    #pragma unroll
    for (int o = 16; o; o >>= 1) { s += __shfl_xor_sync(~0u, s, o); c += __shfl_xor_sync(~0u, c, o); }
    if ((threadIdx.x & 31) == 0) { rs[threadIdx.x >> 5] = s; rc[threadIdx.x >> 5] = c; }
    __syncthreads();
    if (threadIdx.x == 0) {
        float vs = 0.f; int vc = 0;
        for (int i = 0; i < 8; i++) { vs += rs[i]; vc += rc[i]; }
        if (vc < 1) vc = 1;
        *out = vs / (float)vc;
    }
}

// ---------------- host orchestration ----------------
static inline void launch_gemm(const float* A, int lda, const float* Bm, int ldb,
                               float* C, int ldc, int M, int N, int K,
                               const float* bias, int act, int accum) {
    dim3 grid((N + 63) / 64, (M + 63) / 64);
    gemm_k<<<grid, 256>>>(A, lda, Bm, ldb, C, ldc, M, N, K, bias, act, accum);
}

extern "C" void kernel_launch(void* const* d_in, const int* in_sizes, int n_in,
                              void* d_out, int out_size) {
    const int* ids    = (const int*)d_in[0];
    const int* labels = (const int*)d_in[1];
    // params: for each direction, 12 tensors in _mk_params order
    // [emb, norm, inw, convw, convb, xpw, dtw, dtb, Alog, Dp, outw, fnorm]
    const float* P[2][12];
    for (int dir = 0; dir < 2; dir++)
        for (int j = 0; j < 12; j++)
            P[dir][j] = (const float*)d_in[2 + dir * 12 + j];
    const float* lm_w = (const float*)d_in[26];
    float* out = (float*)d_out;
    float* logits = out;  // first BS_*V_ elements; loss at out[out_size-1]

    float *h, *xn, *xz, *xc, *dbcp, *dt, *y, *comb, *rownll;
    cudaGetSymbolAddress((void**)&h,     g_h);
    cudaGetSymbolAddress((void**)&xn,    g_xn);
    cudaGetSymbolAddress((void**)&xz,    g_xz);
    cudaGetSymbolAddress((void**)&xc,    g_xc);
    cudaGetSymbolAddress((void**)&dbcp,  g_dbc);
    cudaGetSymbolAddress((void**)&dt,    g_dt);
    cudaGetSymbolAddress((void**)&y,     g_y);
    cudaGetSymbolAddress((void**)&comb,  g_comb);
    cudaGetSymbolAddress((void**)&rownll, g_rownll);

    for (int dir = 0; dir < 2; dir++) {
        const float* emb   = P[dir][0];
        const float* norm  = P[dir][1];
        const float* inw   = P[dir][2];
        const float* convw = P[dir][3];
        const float* convb = P[dir][4];
        const float* xpw   = P[dir][5];
        const float* dtw   = P[dir][6];
        const float* dtb   = P[dir][7];
        const float* Alog  = P[dir][8];
        const float* Dp    = P[dir][9];
        const float* outw  = P[dir][10];
        const float* fnorm = P[dir][11];

        embed_k<<<BS_, 256>>>(ids, emb, h, dir);

        for (int l = 0; l < L_; l++) {
            // x_norm = rms(h, norm[l])
            rms_k<<<BS_, 256>>>(h, norm + (size_t)l * DM_, xn, DM_, 0, 0);
            // xz = xn @ inw[l].T   [BS, 3072]
            launch_gemm(xn, DM_, inw + (size_t)l * 2 * DI_ * DM_, DM_,
                        xz, XZ_, BS_, XZ_, DM_, nullptr, 0, 0);
            // xc = silu(causal_conv(xz[:, :DI]))
            conv_k<<<(BS_ * DI_ + 255) / 256, 256>>>(xz, convw + (size_t)l * DI_ * KC_,
                                                     convb + (size_t)l * DI_, xc);
            // dbc = xc @ xpw[l].T  [BS, 80]
            launch_gemm(xc, DI_, xpw + (size_t)l * DBC_ * DI_, DI_,
                        dbcp, DBC_, BS_, DBC_, DI_, nullptr, 0, 0);
            // dt = softplus(dbc[:, :48] @ dtw[l].T + dtb[l])  [BS, 1536]
            launch_gemm(dbcp, DBC_, dtw + (size_t)l * DI_ * DR_, DR_,
                        dt, DI_, BS_, DI_, DR_, dtb + (size_t)l * DI_, 1, 0);
            // selective scan fused with +Dp*xc and *silu(z)
            scan_k<<<(B_ * DI_ + 127) / 128, 128>>>(dt, dbcp, xc, xz,
                                                    Alog + (size_t)l * DI_ * DS_,
                                                    Dp + (size_t)l * DI_, y);
            // h += y @ outw[l].T   (residual fused via accumulate)
            launch_gemm(y, DI_, outw + (size_t)l * DM_ * DI_, DI_,
                        h, DM_, BS_, DM_, DI_, nullptr, 0, 1);
        }
        // final rms -> combined (bw half written sequence-reversed)
        rms_k<<<BS_, 256>>>(h, fnorm, comb, 2 * DM_, dir ? DM_ : 0, dir);
    }

    // logits = combined @ lm_w.T   [BS, 32000]
    launch_gemm(comb, 2 * DM_, lm_w, 2 * DM_, logits, V_, BS_, V_, 2 * DM_, nullptr, 0, 0);

    // loss
    loss_row_k<<<BS_, 256>>>(logits, labels, rownll);
    loss_red_k<<<1, 256>>>(rownll, labels, out + (out_size - 1));
}